// round 11
// baseline (speedup 1.0000x reference)
#include <cuda_runtime.h>
#include <cuda_fp16.h>

#define TT   1000
#define NCH  4096

// scratch (no cudaMalloc allowed)
__device__ float g_seq[NCH * TT];     // LSTM input, [chain][t], 16 MB
__device__ float g_feat[NCH * 32];    // [chain][ h_fwd(16) | h_bwd(16) ]

__device__ __forceinline__ float ex2f(float x) {
    float r; asm("ex2.approx.f32 %0, %1;" : "=f"(r) : "f"(x)); return r;
}
__device__ __forceinline__ float rcpf(float x) {
    float r; asm("rcp.approx.f32 %0, %1;" : "=f"(r) : "f"(x)); return r;
}

// 7-MUFU LSTM cell update (batched single-rcp for the 4 gate denominators).
__device__ __forceinline__ void lstm_act(float gi, float gf, float gg, float go,
                                         float& c, float& h) {
    const float NL2E  = -1.4426950408889634f;
    const float N2L2E = -2.8853900817779268f;
    const float ei = ex2f(gi * NL2E);             // MUFU
    const float ef = ex2f(gf * NL2E);             // MUFU
    const float eo = ex2f(go * NL2E);             // MUFU
    const float eg = ex2f(gg * N2L2E);            // MUFU
    const float di = 1.0f + ei, df = 1.0f + ef, dg = 1.0f + eg, dd = 1.0f + eo;
    const float p1 = di * df;
    const float p2 = p1 * dg;
    const float p3 = p2 * dd;
    const float r  = rcpf(p3);                    // MUFU (1 rcp for 4 gates)
    const float so_ = r  * p2;                    // sigmoid(go)
    const float r2  = r  * dd;
    const float tg  = fmaf(2.0f, r2 * p1, -1.0f); // tanh(gg)
    const float r3  = r2 * dg;
    const float sf  = r3 * di;                    // sigmoid(gf)
    const float si  = r3 * df;                    // sigmoid(gi)
    c = fmaf(sf, c, si * tg);
    const float ec = ex2f(c * N2L2E);             // MUFU
    const float tc = fmaf(2.0f, rcpf(1.0f + ec), -1.0f);   // MUFU
    h = so_ * tc;
}

__device__ __forceinline__ unsigned pack_h2(float a, float b) {
    __half2 v = __halves2half2(__float2half_rn(a), __float2half_rn(b));
    return *(unsigned*)&v;
}
// split h into (hi, lo) f16 pair packed in one u32: low16 = hi part
__device__ __forceinline__ unsigned split_pack(float h) {
    const __half hi = __float2half_rn(h);
    const float  hf = __half2float(hi);
    const __half lo = __float2half_rn(h - hf);
    __half2 v = __halves2half2(hi, lo);
    return *(unsigned*)&v;
}

__device__ __forceinline__ void mma16816(float d[4], const unsigned a[4], const unsigned b[2]) {
    asm volatile("mma.sync.aligned.m16n8k16.row.col.f32.f16.f16.f32 "
                 "{%0,%1,%2,%3}, {%4,%5,%6,%7}, {%8,%9}, {%0,%1,%2,%3};"
                 : "+f"(d[0]), "+f"(d[1]), "+f"(d[2]), "+f"(d[3])
                 : "r"(a[0]), "r"(a[1]), "r"(a[2]), "r"(a[3]),
                   "r"(b[0]), "r"(b[1]));
}

__device__ __forceinline__ float gelu_exact(float v) {
    return 0.5f * v * (1.0f + erff(v * 0.70710678118654752f));
}

// ---------------------------------------------------------------------------
// Kernel 1: fused depthwise-conv(5,pad2)+BN+GELU x2. One block per (b,c) row.
// ---------------------------------------------------------------------------
__global__ void __launch_bounds__(256) prep_kernel(
    const float* __restrict__ x,
    const float* __restrict__ c1w, const float* __restrict__ c1b,
    const float* __restrict__ b1g, const float* __restrict__ b1b,
    const float* __restrict__ b1m, const float* __restrict__ b1v,
    const float* __restrict__ c2w, const float* __restrict__ c2b,
    const float* __restrict__ b2g, const float* __restrict__ b2b,
    const float* __restrict__ b2m, const float* __restrict__ b2v)
{
    __shared__ float xs[TT + 4];
    __shared__ float ys[TT + 4];

    const int chain = blockIdx.x;
    const int ch    = chain & 63;
    const int tid   = threadIdx.x;

    if (tid < 2) {
        xs[tid] = 0.0f; xs[TT + 2 + tid] = 0.0f;
        ys[tid] = 0.0f; ys[TT + 2 + tid] = 0.0f;
    }
    const float* xr = x + (size_t)chain * TT;
    for (int t = tid; t < TT; t += 256) xs[t + 2] = xr[t];

    const float w0 = c1w[ch * 5 + 0], w1 = c1w[ch * 5 + 1], w2 = c1w[ch * 5 + 2],
                w3 = c1w[ch * 5 + 3], w4 = c1w[ch * 5 + 4];
    const float s1 = b1g[ch] * rsqrtf(b1v[ch] + 1e-5f);
    const float d1 = (c1b[ch] - b1m[ch]) * s1 + b1b[ch];

    __syncthreads();
    for (int t = tid; t < TT; t += 256) {
        float a = xs[t] * w0;
        a = fmaf(xs[t + 1], w1, a);
        a = fmaf(xs[t + 2], w2, a);
        a = fmaf(xs[t + 3], w3, a);
        a = fmaf(xs[t + 4], w4, a);
        ys[t + 2] = gelu_exact(fmaf(a, s1, d1));
    }

    const float u0 = c2w[ch * 5 + 0], u1 = c2w[ch * 5 + 1], u2 = c2w[ch * 5 + 2],
                u3 = c2w[ch * 5 + 3], u4 = c2w[ch * 5 + 4];
    const float s2 = b2g[ch] * rsqrtf(b2v[ch] + 1e-5f);
    const float d2 = (c2b[ch] - b2m[ch]) * s2 + b2b[ch];

    __syncthreads();
    float* outr = g_seq + (size_t)chain * TT;
    for (int t = tid; t < TT; t += 256) {
        float a = ys[t] * u0;
        a = fmaf(ys[t + 1], u1, a);
        a = fmaf(ys[t + 2], u2, a);
        a = fmaf(ys[t + 3], u3, a);
        a = fmaf(ys[t + 4], u4, a);
        outr[t] = gelu_exact(fmaf(a, s2, d2));
    }
}

// ---------------------------------------------------------------------------
// Kernel 2: LSTM via HMMA, 8 same-direction chains per warp (full N=8).
// R10: depth-1 MMA chains (two independent accumulators, weight-residual
// term dropped — gate err ~1e-5) and register-only h exchange via shfl
// (no smem, no syncwarp).
//
// Lane (g,t): D rows g,g+8 / cols 2t,2t+1 hold ALL FOUR gates for this
// lane's 4 states; activation is in place. h published as split-packed
// f16(hi|lo) registers hp[0..3], pulled by consumers with 8 shfls.
// ---------------------------------------------------------------------------
__global__ void __launch_bounds__(128) lstm_kernel(
    const float* __restrict__ wihf, const float* __restrict__ whhf,
    const float* __restrict__ bihf, const float* __restrict__ bhhf,
    const float* __restrict__ wihr, const float* __restrict__ whhr,
    const float* __restrict__ bihr, const float* __restrict__ bhhr)
{
    const int tid  = threadIdx.x;
    const int lane = tid & 31;
    const int wg   = blockIdx.x * 4 + (tid >> 5);   // 0..1023
    const bool bwd = (wg >= 512);
    const int cb   = 8 * (bwd ? wg - 512 : wg);     // chain base (8 chains)

    const float* wih = bwd ? wihr : wihf;
    const float* whh = bwd ? whhr : whhf;
    const float* bih = bwd ? bihr : bihf;
    const float* bhh = bwd ? bhhr : bhhf;

    const int g = lane >> 2;      // MMA group: D rows g, g+8; B col(chain) g
    const int t = lane & 3;       // MMA thread-in-group: D cols 2t, 2t+1

    // ---- A fragments (f16 W_hh, hi part only), bias and w_ih per gate ----
    unsigned Ahi[4][4];
    float bb0[4], bb1[4], wi0[4], wi1[4];
#pragma unroll
    for (int m = 0; m < 4; m++) {
        const int r0 = m * 16 + g;
        const int r1 = r0 + 8;
        const float* W0 = whh + r0 * 16;
        const float* W1 = whh + r1 * 16;
        Ahi[m][0] = pack_h2(W0[2*t],   W0[2*t+1]);
        Ahi[m][1] = pack_h2(W1[2*t],   W1[2*t+1]);
        Ahi[m][2] = pack_h2(W0[2*t+8], W0[2*t+9]);
        Ahi[m][3] = pack_h2(W1[2*t+8], W1[2*t+9]);
        bb0[m] = bih[r0] + bhh[r0];
        bb1[m] = bih[r1] + bhh[r1];
        wi0[m] = wih[r0];
        wi1[m] = wih[r1];
    }

    // h exchange source lanes: h(unit 2t / 2t+8, chain g) at lane L1,
    // h(unit 2t+1 / 2t+9, chain g) at lane L2; register picked by g&1.
    const int L1  = 8 * t + (g >> 1);
    const int L2  = L1 + 4;
    const bool sel = (g & 1);

    // x staging: lane = 4*chain + substep; coalesced 16B runs per chain
    const int xc  = lane >> 2;          // chain 0..7
    const int xs_ = lane & 3;           // substep 0..3
    const float* seqc = g_seq + (size_t)(cb + xc) * TT;

    // states owned by this lane: q=0 ->(g,2t)  q=1 ->(g,2t+1)
    //                            q=2 ->(g+8,2t) q=3 ->(g+8,2t+1)
    float c4[4]   = {0.0f, 0.0f, 0.0f, 0.0f};
    float hout[4] = {0.0f, 0.0f, 0.0f, 0.0f};
    unsigned hp0 = 0u, hp1 = 0u, hp2 = 0u, hp3 = 0u;  // split-packed h

    for (int r = 0; r < 250; r++) {
        const int tt = r * 4 + xs_;
        const float xv = seqc[bwd ? (TT - 1 - tt) : tt];

#pragma unroll
        for (int s = 0; s < 4; s++) {
            // broadcast x of chains 2t, 2t+1 for this step
            const float xA = __shfl_sync(0xffffffffu, xv, 8 * t + s);
            const float xB = __shfl_sync(0xffffffffu, xv, 8 * t + 4 + s);

            // pull h(t-1) split-packs from owner lanes (no smem, no sync)
            const unsigned a0 = __shfl_sync(0xffffffffu, hp0, L1);
            const unsigned a1 = __shfl_sync(0xffffffffu, hp1, L1);
            const unsigned a2 = __shfl_sync(0xffffffffu, hp2, L1);
            const unsigned a3 = __shfl_sync(0xffffffffu, hp3, L1);
            const unsigned e0 = __shfl_sync(0xffffffffu, hp0, L2);
            const unsigned e1 = __shfl_sync(0xffffffffu, hp1, L2);
            const unsigned e2 = __shfl_sync(0xffffffffu, hp2, L2);
            const unsigned e3 = __shfl_sync(0xffffffffu, hp3, L2);
            const unsigned p0 = sel ? a1 : a0;   // h(unit 2t,   chain g)
            const unsigned p1 = sel ? e1 : e0;   // h(unit 2t+1, chain g)
            const unsigned p2 = sel ? a3 : a2;   // h(unit 2t+8, chain g)
            const unsigned p3 = sel ? e3 : e2;   // h(unit 2t+9, chain g)
            unsigned Bhi[2], Blo[2];
            Bhi[0] = __byte_perm(p0, p1, 0x5410);
            Bhi[1] = __byte_perm(p2, p3, 0x5410);
            Blo[0] = __byte_perm(p0, p1, 0x7632);
            Blo[1] = __byte_perm(p2, p3, 0x7632);

            // two INDEPENDENT accumulators per tile -> MMA dependency depth 1
            float d0[4][4], d1[4][4];
#pragma unroll
            for (int m = 0; m < 4; m++) {
                d0[m][0] = fmaf(wi0[m], xA, bb0[m]);
                d0[m][1] = fmaf(wi0[m], xB, bb0[m]);
                d0[m][2] = fmaf(wi1[m], xA, bb1[m]);
                d0[m][3] = fmaf(wi1[m], xB, bb1[m]);
                d1[m][0] = 0.0f; d1[m][1] = 0.0f; d1[m][2] = 0.0f; d1[m][3] = 0.0f;
            }
#pragma unroll
            for (int m = 0; m < 4; m++) {
                mma16816(d0[m], Ahi[m], Bhi);    // W_hi * h_hi
                mma16816(d1[m], Ahi[m], Blo);    // W_hi * h_lo
            }

            // activate in place; gate m of state q = d0[m][q] + d1[m][q]
#pragma unroll
            for (int q = 0; q < 4; q++) {
                lstm_act(d0[0][q] + d1[0][q], d0[1][q] + d1[1][q],
                         d0[2][q] + d1[2][q], d0[3][q] + d1[3][q],
                         c4[q], hout[q]);
            }

            // publish h for next step (register-only)
            hp0 = split_pack(hout[0]);
            hp1 = split_pack(hout[1]);
            hp2 = split_pack(hout[2]);
            hp3 = split_pack(hout[3]);
        }
    }

    // final h: lane owns (unit g, chains cb+2t, cb+2t+1) and (unit g+8, same)
    const int off = bwd ? 16 : 0;
    g_feat[(cb + 2 * t)     * 32 + off + g]     = hout[0];
    g_feat[(cb + 2 * t + 1) * 32 + off + g]     = hout[1];
    g_feat[(cb + 2 * t)     * 32 + off + g + 8] = hout[2];
    g_feat[(cb + 2 * t + 1) * 32 + off + g + 8] = hout[3];
}

// ---------------------------------------------------------------------------
// Kernel 3: out[n,e] = feat[n,:] . lin_w[e,:] + lin_b[e]
// ---------------------------------------------------------------------------
__global__ void __launch_bounds__(256) linear_kernel(
    const float* __restrict__ lw, const float* __restrict__ lb,
    float* __restrict__ out)
{
    const int idx = blockIdx.x * 256 + threadIdx.x;    // 131072 total
    const int n = idx >> 5;
    const int e = idx & 31;
    const float* f = g_feat + n * 32;
    const float* wp = lw + e * 32;
    float acc = lb[e];
#pragma unroll
    for (int k = 0; k < 32; k++) acc = fmaf(f[k], wp[k], acc);
    out[idx] = acc;
}

// ---------------------------------------------------------------------------
extern "C" void kernel_launch(void* const* d_in, const int* in_sizes, int n_in,
                              void* d_out, int out_size)
{
    const float* x      = (const float*)d_in[0];
    const float* c1w    = (const float*)d_in[1];
    const float* c1b    = (const float*)d_in[2];
    const float* b1g    = (const float*)d_in[3];
    const float* b1b    = (const float*)d_in[4];
    const float* b1m    = (const float*)d_in[5];
    const float* b1v    = (const float*)d_in[6];
    const float* c2w    = (const float*)d_in[7];
    const float* c2b    = (const float*)d_in[8];
    const float* b2g    = (const float*)d_in[9];
    const float* b2b    = (const float*)d_in[10];
    const float* b2m    = (const float*)d_in[11];
    const float* b2v    = (const float*)d_in[12];
    const float* wihf   = (const float*)d_in[13];
    const float* whhf   = (const float*)d_in[14];
    const float* bihf   = (const float*)d_in[15];
    const float* bhhf   = (const float*)d_in[16];
    const float* wihr   = (const float*)d_in[17];
    const float* whhr   = (const float*)d_in[18];
    const float* bihr   = (const float*)d_in[19];
    const float* bhhr   = (const float*)d_in[20];
    const float* lw     = (const float*)d_in[21];
    const float* lb     = (const float*)d_in[22];
    float* out = (float*)d_out;

    prep_kernel<<<NCH, 256>>>(x, c1w, c1b, b1g, b1b, b1m, b1v,
                              c2w, c2b, b2g, b2b, b2m, b2v);
    lstm_kernel<<<256, 128>>>(wihf, whhf, bihf, bhhf,
                              wihr, whhr, bihr, bhhr);
    linear_kernel<<<(NCH * 32) / 256, 256>>>(lw, lb, out);
}

// round 12
// speedup vs baseline: 1.0470x; 1.0470x over previous
#include <cuda_runtime.h>
#include <cuda_fp16.h>

#define TT   1000
#define NCH  4096

// scratch (no cudaMalloc allowed)
__device__ float g_seq[NCH * TT];     // LSTM input, [chain][t], 16 MB
__device__ float g_feat[NCH * 32];    // [chain][ h_fwd(16) | h_bwd(16) ]

__device__ __forceinline__ float ex2f(float x) {
    float r; asm("ex2.approx.f32 %0, %1;" : "=f"(r) : "f"(x)); return r;
}
__device__ __forceinline__ float rcpf(float x) {
    float r; asm("rcp.approx.f32 %0, %1;" : "=f"(r) : "f"(x)); return r;
}

// 7-MUFU LSTM cell update (batched single-rcp for the 4 gate denominators).
__device__ __forceinline__ void lstm_act(float gi, float gf, float gg, float go,
                                         float& c, float& h) {
    const float NL2E  = -1.4426950408889634f;
    const float N2L2E = -2.8853900817779268f;
    const float ei = ex2f(gi * NL2E);             // MUFU
    const float ef = ex2f(gf * NL2E);             // MUFU
    const float eo = ex2f(go * NL2E);             // MUFU
    const float eg = ex2f(gg * N2L2E);            // MUFU
    const float di = 1.0f + ei, df = 1.0f + ef, dg = 1.0f + eg, dd = 1.0f + eo;
    const float p1 = di * df;
    const float p2 = p1 * dg;
    const float p3 = p2 * dd;
    const float r  = rcpf(p3);                    // MUFU (1 rcp for 4 gates)
    const float so_ = r  * p2;                    // sigmoid(go)
    const float r2  = r  * dd;
    const float tg  = fmaf(2.0f, r2 * p1, -1.0f); // tanh(gg)
    const float r3  = r2 * dg;
    const float sf  = r3 * di;                    // sigmoid(gf)
    const float si  = r3 * df;                    // sigmoid(gi)
    c = fmaf(sf, c, si * tg);
    const float ec = ex2f(c * N2L2E);             // MUFU
    const float tc = fmaf(2.0f, rcpf(1.0f + ec), -1.0f);   // MUFU
    h = so_ * tc;
}

__device__ __forceinline__ unsigned pack_h2(float a, float b) {
    __half2 v = __halves2half2(__float2half_rn(a), __float2half_rn(b));
    return *(unsigned*)&v;
}
// split h into (hi, lo) f16 pair packed in one u32: low16 = hi part
__device__ __forceinline__ unsigned split_pack(float h) {
    const __half hi = __float2half_rn(h);
    const float  hf = __half2float(hi);
    const __half lo = __float2half_rn(h - hf);
    __half2 v = __halves2half2(hi, lo);
    return *(unsigned*)&v;
}

__device__ __forceinline__ void mma16816(float d[4], const unsigned a[4], const unsigned b[2]) {
    asm volatile("mma.sync.aligned.m16n8k16.row.col.f32.f16.f16.f32 "
                 "{%0,%1,%2,%3}, {%4,%5,%6,%7}, {%8,%9}, {%0,%1,%2,%3};"
                 : "+f"(d[0]), "+f"(d[1]), "+f"(d[2]), "+f"(d[3])
                 : "r"(a[0]), "r"(a[1]), "r"(a[2]), "r"(a[3]),
                   "r"(b[0]), "r"(b[1]));
}

__device__ __forceinline__ float gelu_exact(float v) {
    return 0.5f * v * (1.0f + erff(v * 0.70710678118654752f));
}

// ---------------------------------------------------------------------------
// Kernel 1: fused depthwise-conv(5,pad2)+BN+GELU x2. One block per (b,c) row.
// ---------------------------------------------------------------------------
__global__ void __launch_bounds__(256) prep_kernel(
    const float* __restrict__ x,
    const float* __restrict__ c1w, const float* __restrict__ c1b,
    const float* __restrict__ b1g, const float* __restrict__ b1b,
    const float* __restrict__ b1m, const float* __restrict__ b1v,
    const float* __restrict__ c2w, const float* __restrict__ c2b,
    const float* __restrict__ b2g, const float* __restrict__ b2b,
    const float* __restrict__ b2m, const float* __restrict__ b2v)
{
    __shared__ float xs[TT + 4];
    __shared__ float ys[TT + 4];

    const int chain = blockIdx.x;
    const int ch    = chain & 63;
    const int tid   = threadIdx.x;

    if (tid < 2) {
        xs[tid] = 0.0f; xs[TT + 2 + tid] = 0.0f;
        ys[tid] = 0.0f; ys[TT + 2 + tid] = 0.0f;
    }
    const float* xr = x + (size_t)chain * TT;
    for (int t = tid; t < TT; t += 256) xs[t + 2] = xr[t];

    const float w0 = c1w[ch * 5 + 0], w1 = c1w[ch * 5 + 1], w2 = c1w[ch * 5 + 2],
                w3 = c1w[ch * 5 + 3], w4 = c1w[ch * 5 + 4];
    const float s1 = b1g[ch] * rsqrtf(b1v[ch] + 1e-5f);
    const float d1 = (c1b[ch] - b1m[ch]) * s1 + b1b[ch];

    __syncthreads();
    for (int t = tid; t < TT; t += 256) {
        float a = xs[t] * w0;
        a = fmaf(xs[t + 1], w1, a);
        a = fmaf(xs[t + 2], w2, a);
        a = fmaf(xs[t + 3], w3, a);
        a = fmaf(xs[t + 4], w4, a);
        ys[t + 2] = gelu_exact(fmaf(a, s1, d1));
    }

    const float u0 = c2w[ch * 5 + 0], u1 = c2w[ch * 5 + 1], u2 = c2w[ch * 5 + 2],
                u3 = c2w[ch * 5 + 3], u4 = c2w[ch * 5 + 4];
    const float s2 = b2g[ch] * rsqrtf(b2v[ch] + 1e-5f);
    const float d2 = (c2b[ch] - b2m[ch]) * s2 + b2b[ch];

    __syncthreads();
    float* outr = g_seq + (size_t)chain * TT;
    for (int t = tid; t < TT; t += 256) {
        float a = ys[t] * u0;
        a = fmaf(ys[t + 1], u1, a);
        a = fmaf(ys[t + 2], u2, a);
        a = fmaf(ys[t + 3], u3, a);
        a = fmaf(ys[t + 4], u4, a);
        outr[t] = gelu_exact(fmaf(a, s2, d2));
    }
}

// ---------------------------------------------------------------------------
// Kernel 2: LSTM via HMMA, 8 same-direction chains per warp (full N=8).
// R11 = R9 exchange (smem h-publish, ONE syncwarp/step) + R10 MMA structure
// (two independent accumulators, depth-1 MMA chains, weight-residual term
// dropped: 8 HMMA/step, gate err ~1e-5).
//
// Lane (g,t): D rows g,g+8 / cols 2t,2t+1 hold ALL FOUR gates for this
// lane's 4 states; activation in place; only h is exchanged.
// ---------------------------------------------------------------------------
__global__ void __launch_bounds__(128) lstm_kernel(
    const float* __restrict__ wihf, const float* __restrict__ whhf,
    const float* __restrict__ bihf, const float* __restrict__ bhhf,
    const float* __restrict__ wihr, const float* __restrict__ whhr,
    const float* __restrict__ bihr, const float* __restrict__ bhhr)
{
    // per-warp h buffer, split-packed f16(hi|lo): [2 parity][16 units][8 ch + pad->20]
    __shared__ unsigned hsp_s[4][2][16][20];

    const int tid  = threadIdx.x;
    const int wid  = tid >> 5;
    const int lane = tid & 31;
    const int wg   = blockIdx.x * 4 + wid;          // 0..1023
    const bool bwd = (wg >= 512);
    const int cb   = 8 * (bwd ? wg - 512 : wg);     // chain base (8 chains)

    const float* wih = bwd ? wihr : wihf;
    const float* whh = bwd ? whhr : whhf;
    const float* bih = bwd ? bihr : bihf;
    const float* bhh = bwd ? bhhr : bhhf;

    unsigned* hspW = &hsp_s[wid][0][0][0];
    for (int i = lane; i < 2 * 16 * 20; i += 32) hspW[i] = 0u;

    const int g = lane >> 2;      // MMA group: D rows g, g+8; B col(chain) g
    const int t = lane & 3;       // MMA thread-in-group: D cols 2t, 2t+1

    // ---- A fragments (f16 W_hh, hi part only), bias and w_ih per gate ----
    unsigned Ahi[4][4];
    float bb0[4], bb1[4], wi0[4], wi1[4];
#pragma unroll
    for (int m = 0; m < 4; m++) {
        const int r0 = m * 16 + g;
        const int r1 = r0 + 8;
        const float* W0 = whh + r0 * 16;
        const float* W1 = whh + r1 * 16;
        Ahi[m][0] = pack_h2(W0[2*t],   W0[2*t+1]);
        Ahi[m][1] = pack_h2(W1[2*t],   W1[2*t+1]);
        Ahi[m][2] = pack_h2(W0[2*t+8], W0[2*t+9]);
        Ahi[m][3] = pack_h2(W1[2*t+8], W1[2*t+9]);
        bb0[m] = bih[r0] + bhh[r0];
        bb1[m] = bih[r1] + bhh[r1];
        wi0[m] = wih[r0];
        wi1[m] = wih[r1];
    }

    // x staging: lane = 4*chain + substep; coalesced 16B runs per chain
    const int xc  = lane >> 2;          // chain 0..7
    const int xs_ = lane & 3;           // substep 0..3
    const float* seqc = g_seq + (size_t)(cb + xc) * TT;

    // states owned by this lane: q=0 ->(g,2t)  q=1 ->(g,2t+1)
    //                            q=2 ->(g+8,2t) q=3 ->(g+8,2t+1)
    float c4[4]   = {0.0f, 0.0f, 0.0f, 0.0f};
    float hout[4] = {0.0f, 0.0f, 0.0f, 0.0f};

    int par = 0;
    for (int r = 0; r < 250; r++) {
        const int tt = r * 4 + xs_;
        const float xv = seqc[bwd ? (TT - 1 - tt) : tt];

#pragma unroll
        for (int s = 0; s < 4; s++) {
            __syncwarp();      // prev step's h writes -> visible for B-build

            // broadcast x of chains 2t, 2t+1 for this step
            const float xA = __shfl_sync(0xffffffffu, xv, 8 * t + s);
            const float xB = __shfl_sync(0xffffffffu, xv, 8 * t + 4 + s);

            // B fragment: h(t-1) for k = 2t,2t+1,2t+8,2t+9 ; chain n = g
            const unsigned* hb = hspW + par * 320;
            const unsigned p0 = hb[(2 * t)     * 20 + g];
            const unsigned p1 = hb[(2 * t + 1) * 20 + g];
            const unsigned p2 = hb[(2 * t + 8) * 20 + g];
            const unsigned p3 = hb[(2 * t + 9) * 20 + g];
            unsigned Bhi[2], Blo[2];
            Bhi[0] = __byte_perm(p0, p1, 0x5410);
            Bhi[1] = __byte_perm(p2, p3, 0x5410);
            Blo[0] = __byte_perm(p0, p1, 0x7632);
            Blo[1] = __byte_perm(p2, p3, 0x7632);

            // two INDEPENDENT accumulators per tile -> MMA dependency depth 1
            float d0[4][4], d1[4][4];
#pragma unroll
            for (int m = 0; m < 4; m++) {
                d0[m][0] = fmaf(wi0[m], xA, bb0[m]);
                d0[m][1] = fmaf(wi0[m], xB, bb0[m]);
                d0[m][2] = fmaf(wi1[m], xA, bb1[m]);
                d0[m][3] = fmaf(wi1[m], xB, bb1[m]);
                d1[m][0] = 0.0f; d1[m][1] = 0.0f; d1[m][2] = 0.0f; d1[m][3] = 0.0f;
            }
#pragma unroll
            for (int m = 0; m < 4; m++) {
                mma16816(d0[m], Ahi[m], Bhi);    // W_hi * h_hi
                mma16816(d1[m], Ahi[m], Blo);    // W_hi * h_lo
            }

            // activate in place; gate m of state q = d0[m][q] + d1[m][q]
#pragma unroll
            for (int q = 0; q < 4; q++) {
                lstm_act(d0[0][q] + d1[0][q], d0[1][q] + d1[1][q],
                         d0[2][q] + d1[2][q], d0[3][q] + d1[3][q],
                         c4[q], hout[q]);
            }

            // publish h for next step's B-build (chains 2t,2t+1 contiguous)
            unsigned* ho = hspW + (par ^ 1) * 320;
            *(uint2*)(ho + g * 20 + 2 * t) =
                make_uint2(split_pack(hout[0]), split_pack(hout[1]));
            *(uint2*)(ho + (g + 8) * 20 + 2 * t) =
                make_uint2(split_pack(hout[2]), split_pack(hout[3]));

            par ^= 1;
        }
    }

    // final h: lane owns (unit g, chains cb+2t, cb+2t+1) and (unit g+8, same)
    const int off = bwd ? 16 : 0;
    g_feat[(cb + 2 * t)     * 32 + off + g]     = hout[0];
    g_feat[(cb + 2 * t + 1) * 32 + off + g]     = hout[1];
    g_feat[(cb + 2 * t)     * 32 + off + g + 8] = hout[2];
    g_feat[(cb + 2 * t + 1) * 32 + off + g + 8] = hout[3];
}

// ---------------------------------------------------------------------------
// Kernel 3: out[n,e] = feat[n,:] . lin_w[e,:] + lin_b[e]
// ---------------------------------------------------------------------------
__global__ void __launch_bounds__(256) linear_kernel(
    const float* __restrict__ lw, const float* __restrict__ lb,
    float* __restrict__ out)
{
    const int idx = blockIdx.x * 256 + threadIdx.x;    // 131072 total
    const int n = idx >> 5;
    const int e = idx & 31;
    const float* f = g_feat + n * 32;
    const float* wp = lw + e * 32;
    float acc = lb[e];
#pragma unroll
    for (int k = 0; k < 32; k++) acc = fmaf(f[k], wp[k], acc);
    out[idx] = acc;
}

// ---------------------------------------------------------------------------
extern "C" void kernel_launch(void* const* d_in, const int* in_sizes, int n_in,
                              void* d_out, int out_size)
{
    const float* x      = (const float*)d_in[0];
    const float* c1w    = (const float*)d_in[1];
    const float* c1b    = (const float*)d_in[2];
    const float* b1g    = (const float*)d_in[3];
    const float* b1b    = (const float*)d_in[4];
    const float* b1m    = (const float*)d_in[5];
    const float* b1v    = (const float*)d_in[6];
    const float* c2w    = (const float*)d_in[7];
    const float* c2b    = (const float*)d_in[8];
    const float* b2g    = (const float*)d_in[9];
    const float* b2b    = (const float*)d_in[10];
    const float* b2m    = (const float*)d_in[11];
    const float* b2v    = (const float*)d_in[12];
    const float* wihf   = (const float*)d_in[13];
    const float* whhf   = (const float*)d_in[14];
    const float* bihf   = (const float*)d_in[15];
    const float* bhhf   = (const float*)d_in[16];
    const float* wihr   = (const float*)d_in[17];
    const float* whhr   = (const float*)d_in[18];
    const float* bihr   = (const float*)d_in[19];
    const float* bhhr   = (const float*)d_in[20];
    const float* lw     = (const float*)d_in[21];
    const float* lb     = (const float*)d_in[22];
    float* out = (float*)d_out;

    prep_kernel<<<NCH, 256>>>(x, c1w, c1b, b1g, b1b, b1m, b1v,
                              c2w, c2b, b2g, b2b, b2m, b2v);
    lstm_kernel<<<256, 128>>>(wihf, whhf, bihf, bhhf,
                              wihr, whhr, bihr, bhhr);
    linear_kernel<<<(NCH * 32) / 256, 256>>>(lw, lb, out);
}